// round 6
// baseline (speedup 1.0000x reference)
#include <cuda_runtime.h>
#include <cstdint>
#include <cstddef>

// Problem dims (fixed by reference)
#define Bb 256
#define Tt 512
#define Dd 64
#define Ll 32
#define Hh 128
#define G4 512   // 4*H

// ---------------- scratch (device globals; no allocation allowed) ----------
__device__ float g_pre[(size_t)Bb * Tt * G4];   // 268 MB: pre-activations

// ---------------- math helpers ---------------------------------------------
__device__ __forceinline__ float sigf(float x) {
    return __fdividef(1.0f, 1.0f + __expf(-x));
}
__device__ __forceinline__ float tanhf_fast(float x) {
    x = fminf(20.0f, fmaxf(-20.0f, x));
    float e = __expf(-2.0f * x);
    return __fdividef(1.0f - e, 1.0f + e);
}

// packed fp32x2 helpers (sm_103a)
__device__ __forceinline__ float2 upk2(unsigned long long v) {
    float2 f;
    asm("mov.b64 {%0, %1}, %2;" : "=f"(f.x), "=f"(f.y) : "l"(v));
    return f;
}
__device__ __forceinline__ void fma2(unsigned long long& d,
                                     unsigned long long a, unsigned long long b) {
    asm("fma.rn.f32x2 %0, %1, %2, %0;" : "+l"(d) : "l"(a), "l"(b));
}

// ============================================================================
// Kernel 1: pre-GEMM with fused static part (R5 body, unchanged — proven).
// ============================================================================
#define PRE_MT 64
#define PRE_NT 128
#define PRE_PAD 65
#define PRE_SMEM (((PRE_MT + PRE_NT) * PRE_PAD + PRE_NT) * 4)   // 50432 bytes

__global__ __launch_bounds__(256) void pre_kernel(
    const float* __restrict__ xd, const float* __restrict__ Wih,
    const float* __restrict__ xs, const float* __restrict__ Wzh,
    const float* __restrict__ bvec)
{
    extern __shared__ float sm[];
    float* xsm   = sm;                                  // [64][65]
    float* wsm   = sm + PRE_MT * PRE_PAD;               // [128][65]
    float* svrow = sm + (PRE_MT + PRE_NT) * PRE_PAD;    // [128]

    int t  = threadIdx.x;
    int m0 = blockIdx.x * PRE_MT;
    int n0 = blockIdx.y * PRE_NT;
    int bb = m0 >> 9;   // T = 512

    {
        const float4* xg = (const float4*)(xd + (size_t)m0 * Dd);
        for (int i = t; i < PRE_MT * (Dd / 4); i += 256) {
            int row = i >> 4, dq = i & 15;
            float4 v = xg[row * 16 + dq];
            float* dst = xsm + row * PRE_PAD + dq * 4;
            dst[0] = v.x; dst[1] = v.y; dst[2] = v.z; dst[3] = v.w;
        }
    }
    {
        const float4* wg = (const float4*)(Wih + (size_t)n0 * Dd);
        for (int i = t; i < PRE_NT * (Dd / 4); i += 256) {
            int row = i >> 4, dq = i & 15;
            float4 v = wg[row * 16 + dq];
            float* dst = wsm + row * PRE_PAD + dq * 4;
            dst[0] = v.x; dst[1] = v.y; dst[2] = v.z; dst[3] = v.w;
        }
    }
    if (t < PRE_NT) {
        int gn = n0 + t;
        float acc = bvec[gn];
        const float* w = Wzh + gn * Ll;
        const float* xr = xs + bb * Ll;
#pragma unroll
        for (int l = 0; l < Ll; l++) acc += xr[l] * w[l];
        svrow[t] = acc;
    }
    __syncthreads();

    int tn = t & 15;
    int tm = t >> 4;

    float acc[4][8];
#pragma unroll
    for (int i = 0; i < 4; i++)
#pragma unroll
        for (int jj = 0; jj < 8; jj++) acc[i][jj] = 0.0f;

#pragma unroll 8
    for (int k = 0; k < Dd; k++) {
        float a[4], b[8];
#pragma unroll
        for (int i = 0; i < 4; i++)  a[i]  = xsm[(tm + 16 * i) * PRE_PAD + k];
#pragma unroll
        for (int jj = 0; jj < 8; jj++) b[jj] = wsm[(tn + 16 * jj) * PRE_PAD + k];
#pragma unroll
        for (int i = 0; i < 4; i++)
#pragma unroll
            for (int jj = 0; jj < 8; jj++) acc[i][jj] += a[i] * b[jj];
    }

    float sv[8];
#pragma unroll
    for (int jj = 0; jj < 8; jj++) sv[jj] = svrow[tn + 16 * jj];
#pragma unroll
    for (int i = 0; i < 4; i++) {
        float* orow = g_pre + (size_t)(m0 + tm + 16 * i) * G4 + n0;
#pragma unroll
        for (int jj = 0; jj < 8; jj++) orow[tn + 16 * jj] = acc[i][jj] + sv[jj];
    }
}

// ============================================================================
// Kernel 2: persistent LSTM scan — independent CTAs, 2 batch rows each.
//   R5 structure + this round:
//   - matvec on fma.rn.f32x2 (128 packed FMA/thread vs 256 scalar)
//   - gate activations computed by the matvec threads (16-warp MUFU spread;
//     warp-uniform gate type, same values as before)
//   - producer barrier split: warps 8..15 bar.arrive on the gate barrier
// ============================================================================
#define NCH 24   // smem W chunks of 4 d-values (d 0..95)
#define OFF_W    0                        // 24 * 512 * 4 floats (192KB)
#define OFF_H    (NCH * 2048)             // h[2][128]
#define OFF_G    (OFF_H + 256)            // act[2][512]
#define OFF_RED  (OFF_G + 1024)           // red[8]
#define SCAN_SMEM ((OFF_RED + 8) * 4)     // 201760 bytes

__global__ void __launch_bounds__(512, 1)
scan_kernel(const float* __restrict__ Whh, const float* __restrict__ Wout,
            const float* __restrict__ bout, float* __restrict__ out)
{
    extern __shared__ float sm[];
    int tid = threadIdx.x;
    int b0  = blockIdx.x * 2;
    int j   = tid;                 // gate-column index 0..511
    bool is_tanh_gate = ((j >> 7) == 2);   // warp-uniform

    // ---- W d 0..95 into smem: Wv[c][j][q] = W_hh[j][4c+q]
#pragma unroll 4
    for (int c = 0; c < NCH; c++) {
        float4 v = *(const float4*)(Whh + (size_t)j * 128 + c * 4);
        float* dst = sm + OFF_W + c * 2048 + j * 4;
        dst[0] = v.x; dst[1] = v.y; dst[2] = v.z; dst[3] = v.w;
    }
    // ---- W d 96..127 into registers as f32x2 pairs (16 ULL = 32 regs)
    unsigned long long wreg[16];
    {
        const float* ws = Whh + (size_t)j * 128 + 96;
#pragma unroll
        for (int c = 0; c < 8; c++) {
            ulonglong2 v = *(const ulonglong2*)(ws + c * 4);
            wreg[2 * c]     = v.x;
            wreg[2 * c + 1] = v.y;
        }
    }
    if (tid < 256) sm[OFF_H + tid] = 0.0f;
    __syncthreads();

    int r2 = tid >> 7;        // row 0..1 (update role, tid < 256)
    int k  = tid & 127;       // hidden index (update role)

    float cst = 0.0f;
    float wo  = (tid < 256) ? Wout[k] : 0.0f;
    float bo  = bout[0];

    const float* pre0 = g_pre + ((size_t)(b0 + 0) * Tt) * G4 + j;
    const float* pre1 = g_pre + ((size_t)(b0 + 1) * Tt) * G4 + j;
    const float* hsh  = sm + OFF_H;

    for (int t = 0; t < Tt; t++) {
        float p0 = pre0[(size_t)t * G4];
        float p1 = pre1[(size_t)t * G4];

        // full matvec on f32x2: acc_r = sum_d W[j][d] * h[r][d]
        unsigned long long a0 = 0ull, a1 = 0ull;
#pragma unroll
        for (int c = 0; c < NCH; c++) {          // d 0..95 (smem weights)
            ulonglong2 w  = *(const ulonglong2*)(sm + OFF_W + c * 2048 + j * 4);
            ulonglong2 h0 = *(const ulonglong2*)(hsh + 0 * 128 + c * 4);
            ulonglong2 h1 = *(const ulonglong2*)(hsh + 1 * 128 + c * 4);
            fma2(a0, w.x, h0.x);  fma2(a0, w.y, h0.y);
            fma2(a1, w.x, h1.x);  fma2(a1, w.y, h1.y);
        }
#pragma unroll
        for (int c = 0; c < 8; c++) {            // d 96..127 (register weights)
            ulonglong2 h0 = *(const ulonglong2*)(hsh + 0 * 128 + 96 + c * 4);
            ulonglong2 h1 = *(const ulonglong2*)(hsh + 1 * 128 + 96 + c * 4);
            fma2(a0, wreg[2 * c], h0.x);  fma2(a0, wreg[2 * c + 1], h0.y);
            fma2(a1, wreg[2 * c], h1.x);  fma2(a1, wreg[2 * c + 1], h1.y);
        }
        float2 f0 = upk2(a0), f1 = upk2(a1);
        float g0 = p0 + (f0.x + f0.y);
        float g1 = p1 + (f1.x + f1.y);

        // gate activation here (16-warp MUFU spread; warp-uniform branch)
        float act0, act1;
        if (is_tanh_gate) { act0 = tanhf_fast(g0); act1 = tanhf_fast(g1); }
        else              { act0 = sigf(g0);       act1 = sigf(g1);       }
        sm[OFF_G + 0 * 512 + j] = act0;
        sm[OFF_G + 1 * 512 + j] = act1;

        // gate barrier: producers = all; consumers = warps 0..7
        if (tid < 256) {
            asm volatile("bar.sync 1, 512;" ::: "memory");

            float ai = sm[OFF_G + r2 * 512 + k];
            float af = sm[OFF_G + r2 * 512 + 128 + k];
            float ag = sm[OFF_G + r2 * 512 + 256 + k];
            float ao = sm[OFF_G + r2 * 512 + 384 + k];
            cst = af * cst + ai * ag;
            float hval = ao * tanhf_fast(cst);
            sm[OFF_H + r2 * 128 + k] = hval;

            // fused O=1 head: warp-reduce hval*wo (warps 0..7)
            float v = hval * wo;
            v += __shfl_down_sync(0xffffffffu, v, 16);
            v += __shfl_down_sync(0xffffffffu, v, 8);
            v += __shfl_down_sync(0xffffffffu, v, 4);
            v += __shfl_down_sync(0xffffffffu, v, 2);
            v += __shfl_down_sync(0xffffffffu, v, 1);
            if ((tid & 31) == 0) sm[OFF_RED + (tid >> 5)] = v;
        } else {
            asm volatile("bar.arrive 1, 512;" ::: "memory");
        }
        __syncthreads();   // h + red ready; also fences act[] overwrite

        if (tid < 2) {
            const float* rd = sm + OFF_RED + tid * 4;
            out[(size_t)(b0 + tid) * Tt + t] = rd[0] + rd[1] + rd[2] + rd[3] + bo;
        }
    }
}

// ============================================================================
// launch
// ============================================================================
extern "C" void kernel_launch(void* const* d_in, const int* in_sizes, int n_in,
                              void* d_out, int out_size)
{
    const float* x_dyn = (const float*)d_in[0];
    const float* x_sta = (const float*)d_in[1];
    const float* W_ih  = (const float*)d_in[2];
    const float* W_hh  = (const float*)d_in[3];
    const float* W_zh  = (const float*)d_in[4];
    const float* bvec  = (const float*)d_in[5];
    const float* W_out = (const float*)d_in[6];
    const float* b_out = (const float*)d_in[7];
    float* out = (float*)d_out;

    (void)in_sizes; (void)n_in; (void)out_size;

    cudaFuncSetAttribute(pre_kernel,
                         cudaFuncAttributeMaxDynamicSharedMemorySize, PRE_SMEM);
    cudaFuncSetAttribute(scan_kernel,
                         cudaFuncAttributeMaxDynamicSharedMemorySize, SCAN_SMEM);

    dim3 pre_grid((Bb * Tt) / PRE_MT, G4 / PRE_NT);   // 2048 x 4
    pre_kernel<<<pre_grid, 256, PRE_SMEM>>>(x_dyn, W_ih, x_sta, W_zh, bvec);

    scan_kernel<<<128, 512, SCAN_SMEM>>>(W_hh, W_out, b_out, out);
}